// round 1
// baseline (speedup 1.0000x reference)
#include <cuda_runtime.h>
#include <cstdint>

#define B_    8
#define V_    100000
#define FIN_  32
#define K_    4
#define FOUT_ 64
#define E_    800000
#define TPV   256            // features per vertex = FIN_*B_
#define VF    (V_ * TPV)     // floats per Chebyshev order

// ---- scratch (static device globals; no allocation) ----
__device__ float d_x[4ull * VF];          // x0..x3, layout [k][v][f*8+b]
__device__ int   d_counts[V_];
__device__ int   d_rowptr[V_ + 1];
__device__ int   d_cursor[V_];
__device__ int   d_ccol[E_];
__device__ float d_cval[E_];

// ---------------- packed f32x2 helpers (Blackwell) ----------------
__device__ __forceinline__ unsigned long long pack2(float a, float b) {
    unsigned long long r;
    asm("mov.b64 %0, {%1, %2};" : "=l"(r) : "f"(a), "f"(b));
    return r;
}
__device__ __forceinline__ unsigned long long fma2(unsigned long long x,
                                                   unsigned long long y,
                                                   unsigned long long c) {
    unsigned long long r;
    asm("fma.rn.f32x2 %0, %1, %2, %3;" : "=l"(r) : "l"(x), "l"(y), "l"(c));
    return r;
}
__device__ __forceinline__ void unpack2(unsigned long long v, float& lo, float& hi) {
    asm("mov.b64 {%0, %1}, %2;" : "=f"(lo), "=f"(hi) : "l"(v));
}

// ---------------- 1. transpose inputs[B,V,Fin] -> x0[v][f*8+b] ----------------
__global__ void transpose_kernel(const float* __restrict__ in) {
    int idx = blockIdx.x * blockDim.x + threadIdx.x;
    if (idx >= VF) return;
    int v = idx >> 8;
    int r = idx & 255;
    int f = r >> 3;
    int b = r & 7;
    d_x[idx] = in[((size_t)b * V_ + v) * FIN_ + f];
}

// ---------------- 2. CSR build ----------------
__global__ void zero_counts_kernel() {
    int i = blockIdx.x * blockDim.x + threadIdx.x;
    if (i < V_) d_counts[i] = 0;
}

__global__ void hist_kernel(const int* __restrict__ rows) {
    int e = blockIdx.x * blockDim.x + threadIdx.x;
    if (e < E_) atomicAdd(&d_counts[rows[e]], 1);
}

// single-block exclusive scan of counts -> rowptr (+ cursor copy)
__global__ void scan_kernel() {
    __shared__ int sums[1024];
    const int t = threadIdx.x;
    const int chunk = (V_ + 1023) / 1024;
    int start = t * chunk;
    int end = start + chunk;
    if (end > V_) end = V_;
    int s = 0;
    for (int i = start; i < end; ++i) s += d_counts[i];
    sums[t] = s;
    __syncthreads();
    // Hillis-Steele inclusive scan
    for (int off = 1; off < 1024; off <<= 1) {
        int v = 0;
        if (t >= off) v = sums[t - off];
        __syncthreads();
        if (t >= off) sums[t] += v;
        __syncthreads();
    }
    int run = (t == 0) ? 0 : sums[t - 1];
    for (int i = start; i < end; ++i) {
        d_rowptr[i] = run;
        d_cursor[i] = run;
        run += d_counts[i];
    }
    if (end == V_) d_rowptr[V_] = run;   // == E_
}

__global__ void scatter_kernel(const int* __restrict__ rows,
                               const int* __restrict__ cols,
                               const float* __restrict__ vals) {
    int e = blockIdx.x * blockDim.x + threadIdx.x;
    if (e >= E_) return;
    int r = rows[e];
    int p = atomicAdd(&d_cursor[r], 1);
    d_ccol[p] = cols[e];
    d_cval[p] = vals[e];
}

// ---------------- 3. SpMM + Chebyshev recurrence: y = alpha*(L x) + beta*z ----------------
__global__ __launch_bounds__(TPV) void spmm_kernel(const float* __restrict__ x,
                                                   const float* __restrict__ z,
                                                   float* __restrict__ y,
                                                   float alpha, float beta) {
    const int v = blockIdx.x;
    const int t = threadIdx.x;
    const int s = d_rowptr[v];
    const int e = d_rowptr[v + 1];
    float acc0 = 0.f, acc1 = 0.f;
    int i = s;
    for (; i + 1 < e; i += 2) {
        int   c0 = d_ccol[i],     c1 = d_ccol[i + 1];
        float w0 = d_cval[i],     w1 = d_cval[i + 1];
        acc0 = fmaf(w0, __ldg(&x[(size_t)c0 * TPV + t]), acc0);
        acc1 = fmaf(w1, __ldg(&x[(size_t)c1 * TPV + t]), acc1);
    }
    if (i < e) {
        acc0 = fmaf(d_cval[i], __ldg(&x[(size_t)d_ccol[i] * TPV + t]), acc0);
    }
    float out = alpha * (acc0 + acc1);
    if (beta != 0.f) out = fmaf(beta, z[(size_t)v * TPV + t], out);
    y[(size_t)v * TPV + t] = out;
}

// ---------------- 4. einsum: out[b,v,o] = sum_{k,f} x_k[v,f,b] * W[f,k,o] + bias[o] ----------------
// 256 threads = 4 vertex-groups of 64 threads (one thread per output column o).
// 8 batch values per thread packed into 4 f32x2 accumulators (FFMA2 = 2x fp32 rate).
__global__ __launch_bounds__(256) void einsum_kernel(const float* __restrict__ w,
                                                     const float* __restrict__ bias,
                                                     float* __restrict__ out) {
    __shared__ float ws[FIN_ * K_ * FOUT_];            // 8192 floats = 32 KB
    __shared__ __align__(16) float xs[4][4 * TPV];     // 4 groups x 1024 floats = 16 KB

    const int t = threadIdx.x;
    for (int i = t; i < FIN_ * K_ * FOUT_; i += 256) ws[i] = w[i];

    const int g = t >> 6;      // vertex group within block
    const int o = t & 63;      // output column
    const float bo = __ldg(&bias[o]);
    const int v = blockIdx.x * 4 + g;   // grid = V_/4 blocks, V_ % 4 == 0

    // stage this vertex's 4x256 Chebyshev features into shared
    #pragma unroll
    for (int k = 0; k < K_; k++) {
        float4 val = *reinterpret_cast<const float4*>(&d_x[((size_t)k * V_ + v) * TPV + o * 4]);
        *reinterpret_cast<float4*>(&xs[g][k * TPV + o * 4]) = val;
    }
    __syncthreads();

    unsigned long long a0 = 0ull, a1 = 0ull, a2 = 0ull, a3 = 0ull; // (b0,b1)(b2,b3)(b4,b5)(b6,b7)
    #pragma unroll
    for (int k = 0; k < K_; k++) {
        #pragma unroll 4
        for (int f = 0; f < FIN_; f++) {
            float wv = ws[f * (K_ * FOUT_) + k * FOUT_ + o];     // conflict-free across o
            unsigned long long wp = pack2(wv, wv);
            const ulonglong2* xp =
                reinterpret_cast<const ulonglong2*>(&xs[g][k * TPV + f * 8]); // broadcast LDS
            ulonglong2 p0 = xp[0];   // b0..b3
            ulonglong2 p1 = xp[1];   // b4..b7
            a0 = fma2(p0.x, wp, a0);
            a1 = fma2(p0.y, wp, a1);
            a2 = fma2(p1.x, wp, a2);
            a3 = fma2(p1.y, wp, a3);
        }
    }

    float rb[8];
    unpack2(a0, rb[0], rb[1]);
    unpack2(a1, rb[2], rb[3]);
    unpack2(a2, rb[4], rb[5]);
    unpack2(a3, rb[6], rb[7]);
    #pragma unroll
    for (int b = 0; b < B_; b++)
        out[((size_t)b * V_ + v) * FOUT_ + o] = rb[b] + bo;
}

// ---------------- launch ----------------
extern "C" void kernel_launch(void* const* d_in, const int* in_sizes, int n_in,
                              void* d_out, int out_size) {
    const float* inputs = (const float*)d_in[0];
    const int*   rows   = (const int*)d_in[1];
    const int*   cols   = (const int*)d_in[2];
    const float* vals   = (const float*)d_in[3];
    const float* weight = (const float*)d_in[4];
    const float* bias   = (const float*)d_in[5];
    float* out = (float*)d_out;

    float* xbase;
    cudaGetSymbolAddress((void**)&xbase, d_x);

    // 1. x0 = transpose(inputs)
    transpose_kernel<<<(VF + 255) / 256, 256>>>(inputs);

    // 2. CSR build
    zero_counts_kernel<<<(V_ + 255) / 256, 256>>>();
    hist_kernel<<<(E_ + 255) / 256, 256>>>(rows);
    scan_kernel<<<1, 1024>>>();
    scatter_kernel<<<(E_ + 255) / 256, 256>>>(rows, cols, vals);

    // 3. Chebyshev recurrence
    float* x0 = xbase;
    float* x1 = xbase + (size_t)VF;
    float* x2 = xbase + 2 * (size_t)VF;
    float* x3 = xbase + 3 * (size_t)VF;
    spmm_kernel<<<V_, TPV>>>(x0, x0, x1, 1.0f, 0.0f);   // x1 = L x0
    spmm_kernel<<<V_, TPV>>>(x1, x0, x2, 2.0f, -1.0f);  // x2 = 2 L x1 - x0
    spmm_kernel<<<V_, TPV>>>(x2, x1, x3, 2.0f, -1.0f);  // x3 = 2 L x2 - x1

    // 4. einsum + bias
    einsum_kernel<<<V_ / 4, 256>>>(weight, bias, out);
}

// round 2
// speedup vs baseline: 1.6710x; 1.6710x over previous
#include <cuda_runtime.h>
#include <cstdint>

#define B_    8
#define V_    100000
#define FIN_  32
#define K_    4
#define FOUT_ 64
#define E_    800000
#define TPV   256            // features per vertex = FIN_*B_
#define VF    (V_ * TPV)     // floats per Chebyshev order
#define SCAN_B ((V_ + 1023) / 1024)   // 98 scan blocks

// ---- scratch (static device globals; no allocation) ----
__device__ float d_x[4ull * VF];          // x0..x3, layout [k][v][f*8+b]
__device__ int   d_counts[V_];
__device__ int   d_rowptr[V_ + 1];
__device__ int   d_cursor[V_];
__device__ int   d_ccol[E_];
__device__ float d_cval[E_];
__device__ int   d_bsum[SCAN_B];

// ---------------- packed f32x2 helpers (Blackwell) ----------------
__device__ __forceinline__ unsigned long long pack2(float a, float b) {
    unsigned long long r;
    asm("mov.b64 %0, {%1, %2};" : "=l"(r) : "f"(a), "f"(b));
    return r;
}
__device__ __forceinline__ unsigned long long fma2(unsigned long long x,
                                                   unsigned long long y,
                                                   unsigned long long c) {
    unsigned long long r;
    asm("fma.rn.f32x2 %0, %1, %2, %3;" : "=l"(r) : "l"(x), "l"(y), "l"(c));
    return r;
}
__device__ __forceinline__ void unpack2(unsigned long long v, float& lo, float& hi) {
    asm("mov.b64 {%0, %1}, %2;" : "=f"(lo), "=f"(hi) : "l"(v));
}

// ---------------- 1. tiled transpose inputs[B,V,Fin] -> x0[v][f*8+b] ----------------
// One block = 32 vertices. Coalesced reads per batch slice, coalesced float4 writes.
__global__ __launch_bounds__(1024) void transpose_kernel(const float* __restrict__ in) {
    __shared__ float tile[32 * 256 + 32];   // [v][f*8+b], small pad
    const int v0 = blockIdx.x * 32;
    const int t = threadIdx.x;
    // load: 8 batch slices of 32v x 32f, coalesced on f
    const int lv = t >> 5;        // 0..31 vertex within tile
    const int lf = t & 31;        // 0..31 feature
    #pragma unroll
    for (int b = 0; b < B_; b++) {
        float val = in[((size_t)b * V_ + (v0 + lv)) * FIN_ + lf];
        tile[lv * 256 + lf * 8 + b] = val;
    }
    __syncthreads();
    // store: 32 * 256 floats = 2048 float4; 1024 threads x 2
    float4* dst = reinterpret_cast<float4*>(&d_x[(size_t)v0 * TPV]);
    const float4* src = reinterpret_cast<const float4*>(tile);
    dst[t] = src[t];
    dst[t + 1024] = src[t + 1024];
}

// ---------------- 2. CSR build ----------------
__global__ void zero_counts_kernel() {
    int i = blockIdx.x * blockDim.x + threadIdx.x;
    if (i < V_) d_counts[i] = 0;
}

__global__ void hist_kernel(const int* __restrict__ rows) {
    int e = blockIdx.x * blockDim.x + threadIdx.x;
    if (e < E_) atomicAdd(&d_counts[rows[e]], 1);
}

// block-wide exclusive scan over 1024 threads, returns exclusive prefix; *total = block sum
__device__ __forceinline__ int block_exscan(int v, int* total) {
    const int lane = threadIdx.x & 31;
    const int wid = threadIdx.x >> 5;
    int inc = v;
    #pragma unroll
    for (int o = 1; o < 32; o <<= 1) {
        int n = __shfl_up_sync(0xffffffffu, inc, o);
        if (lane >= o) inc += n;
    }
    __shared__ int wsum[32];
    if (lane == 31) wsum[wid] = inc;
    __syncthreads();
    if (wid == 0) {
        int s = wsum[lane];
        #pragma unroll
        for (int o = 1; o < 32; o <<= 1) {
            int n = __shfl_up_sync(0xffffffffu, s, o);
            if (lane >= o) s += n;
        }
        wsum[lane] = s;
    }
    __syncthreads();
    int excl = inc - v + (wid ? wsum[wid - 1] : 0);
    *total = wsum[31];
    return excl;
}

// pass 1: per-block local exclusive scan into rowptr, block sums into d_bsum
__global__ __launch_bounds__(1024) void scan1_kernel() {
    int i = blockIdx.x * 1024 + threadIdx.x;
    int v = (i < V_) ? d_counts[i] : 0;
    int total;
    int excl = block_exscan(v, &total);
    if (i < V_) d_rowptr[i] = excl;
    if (threadIdx.x == 0) d_bsum[blockIdx.x] = total;
}

// pass 2: single small block scans the 98 block sums (exclusive, in place)
__global__ void scan2_kernel() {
    __shared__ int s[128];
    int t = threadIdx.x;
    s[t] = (t < SCAN_B) ? d_bsum[t] : 0;
    __syncthreads();
    // Hillis-Steele inclusive
    #pragma unroll
    for (int o = 1; o < 128; o <<= 1) {
        int v = (t >= o) ? s[t - o] : 0;
        __syncthreads();
        s[t] += v;
        __syncthreads();
    }
    if (t < SCAN_B) d_bsum[t] = (t == 0) ? 0 : s[t - 1];
}

// pass 3: add block offsets, mirror to cursor, cap rowptr
__global__ __launch_bounds__(1024) void scan3_kernel() {
    int i = blockIdx.x * 1024 + threadIdx.x;
    if (i < V_) {
        int r = d_rowptr[i] + d_bsum[blockIdx.x];
        d_rowptr[i] = r;
        d_cursor[i] = r;
    }
    if (i == 0) d_rowptr[V_] = E_;
}

__global__ void scatter_kernel(const int* __restrict__ rows,
                               const int* __restrict__ cols,
                               const float* __restrict__ vals) {
    int e = blockIdx.x * blockDim.x + threadIdx.x;
    if (e >= E_) return;
    int r = rows[e];
    int p = atomicAdd(&d_cursor[r], 1);
    d_ccol[p] = cols[e];
    d_cval[p] = vals[e];
}

// ---------------- 3. SpMM + Chebyshev recurrence: y = alpha*(L x) + beta*z ----------------
// 64 threads per vertex (float4 each), 4 vertices per 256-thread block.
__global__ __launch_bounds__(256) void spmm_kernel(const float* __restrict__ x,
                                                   const float* __restrict__ z,
                                                   float* __restrict__ y,
                                                   float alpha, float beta) {
    const int g = threadIdx.x >> 6;          // vertex within block
    const int t = threadIdx.x & 63;          // float4 lane
    const int v = blockIdx.x * 4 + g;
    const int s = __ldg(&d_rowptr[v]);
    const int e = __ldg(&d_rowptr[v + 1]);

    float4 a0 = make_float4(0.f, 0.f, 0.f, 0.f);
    float4 a1 = make_float4(0.f, 0.f, 0.f, 0.f);
    int i = s;
    for (; i + 1 < e; i += 2) {
        int   c0 = __ldg(&d_ccol[i]);
        int   c1 = __ldg(&d_ccol[i + 1]);
        float w0 = __ldg(&d_cval[i]);
        float w1 = __ldg(&d_cval[i + 1]);
        float4 x0 = __ldg(reinterpret_cast<const float4*>(&x[(size_t)c0 * TPV + t * 4]));
        float4 x1 = __ldg(reinterpret_cast<const float4*>(&x[(size_t)c1 * TPV + t * 4]));
        a0.x = fmaf(w0, x0.x, a0.x); a0.y = fmaf(w0, x0.y, a0.y);
        a0.z = fmaf(w0, x0.z, a0.z); a0.w = fmaf(w0, x0.w, a0.w);
        a1.x = fmaf(w1, x1.x, a1.x); a1.y = fmaf(w1, x1.y, a1.y);
        a1.z = fmaf(w1, x1.z, a1.z); a1.w = fmaf(w1, x1.w, a1.w);
    }
    if (i < e) {
        int   c0 = __ldg(&d_ccol[i]);
        float w0 = __ldg(&d_cval[i]);
        float4 x0 = __ldg(reinterpret_cast<const float4*>(&x[(size_t)c0 * TPV + t * 4]));
        a0.x = fmaf(w0, x0.x, a0.x); a0.y = fmaf(w0, x0.y, a0.y);
        a0.z = fmaf(w0, x0.z, a0.z); a0.w = fmaf(w0, x0.w, a0.w);
    }
    float4 r;
    r.x = alpha * (a0.x + a1.x);
    r.y = alpha * (a0.y + a1.y);
    r.z = alpha * (a0.z + a1.z);
    r.w = alpha * (a0.w + a1.w);
    if (beta != 0.f) {
        float4 zv = __ldg(reinterpret_cast<const float4*>(&z[(size_t)v * TPV + t * 4]));
        r.x = fmaf(beta, zv.x, r.x);
        r.y = fmaf(beta, zv.y, r.y);
        r.z = fmaf(beta, zv.z, r.z);
        r.w = fmaf(beta, zv.w, r.w);
    }
    *reinterpret_cast<float4*>(&y[(size_t)v * TPV + t * 4]) = r;
}

// ---------------- 4. einsum: out[b,v,o] = sum_{k,f} x_k[v,f,b] * W[f,k,o] + bias[o] ----------------
// 256 threads = 4 vertex-groups of 64 threads (one thread per output column o).
// 8 batch values per thread packed into 4 f32x2 accumulators (FFMA2 = 2x fp32 rate).
__global__ __launch_bounds__(256) void einsum_kernel(const float* __restrict__ w,
                                                     const float* __restrict__ bias,
                                                     float* __restrict__ out) {
    __shared__ float ws[FIN_ * K_ * FOUT_];            // 8192 floats = 32 KB
    __shared__ __align__(16) float xs[4][4 * TPV];     // 4 groups x 1024 floats = 16 KB

    const int t = threadIdx.x;
    for (int i = t; i < FIN_ * K_ * FOUT_; i += 256) ws[i] = w[i];

    const int g = t >> 6;      // vertex group within block
    const int o = t & 63;      // output column
    const float bo = __ldg(&bias[o]);
    const int v = blockIdx.x * 4 + g;   // grid = V_/4 blocks, V_ % 4 == 0

    // stage this vertex's 4x256 Chebyshev features into shared
    #pragma unroll
    for (int k = 0; k < K_; k++) {
        float4 val = *reinterpret_cast<const float4*>(&d_x[((size_t)k * V_ + v) * TPV + o * 4]);
        *reinterpret_cast<float4*>(&xs[g][k * TPV + o * 4]) = val;
    }
    __syncthreads();

    unsigned long long a0 = 0ull, a1 = 0ull, a2 = 0ull, a3 = 0ull; // (b0,b1)(b2,b3)(b4,b5)(b6,b7)
    #pragma unroll
    for (int k = 0; k < K_; k++) {
        #pragma unroll 4
        for (int f = 0; f < FIN_; f++) {
            float wv = ws[f * (K_ * FOUT_) + k * FOUT_ + o];     // conflict-free across o
            unsigned long long wp = pack2(wv, wv);
            const ulonglong2* xp =
                reinterpret_cast<const ulonglong2*>(&xs[g][k * TPV + f * 8]); // broadcast LDS
            ulonglong2 p0 = xp[0];   // b0..b3
            ulonglong2 p1 = xp[1];   // b4..b7
            a0 = fma2(p0.x, wp, a0);
            a1 = fma2(p0.y, wp, a1);
            a2 = fma2(p1.x, wp, a2);
            a3 = fma2(p1.y, wp, a3);
        }
    }

    float rb[8];
    unpack2(a0, rb[0], rb[1]);
    unpack2(a1, rb[2], rb[3]);
    unpack2(a2, rb[4], rb[5]);
    unpack2(a3, rb[6], rb[7]);
    #pragma unroll
    for (int b = 0; b < B_; b++)
        out[((size_t)b * V_ + v) * FOUT_ + o] = rb[b] + bo;
}

// ---------------- launch ----------------
extern "C" void kernel_launch(void* const* d_in, const int* in_sizes, int n_in,
                              void* d_out, int out_size) {
    const float* inputs = (const float*)d_in[0];
    const int*   rows   = (const int*)d_in[1];
    const int*   cols   = (const int*)d_in[2];
    const float* vals   = (const float*)d_in[3];
    const float* weight = (const float*)d_in[4];
    const float* bias   = (const float*)d_in[5];
    float* out = (float*)d_out;

    float* xbase;
    cudaGetSymbolAddress((void**)&xbase, d_x);

    // 1. x0 = transpose(inputs)   (V_ = 100000 = 3125 * 32 vertices/block)
    transpose_kernel<<<V_ / 32, 1024>>>(inputs);

    // 2. CSR build
    zero_counts_kernel<<<(V_ + 255) / 256, 256>>>();
    hist_kernel<<<(E_ + 255) / 256, 256>>>(rows);
    scan1_kernel<<<SCAN_B, 1024>>>();
    scan2_kernel<<<1, 128>>>();
    scan3_kernel<<<SCAN_B, 1024>>>();
    scatter_kernel<<<(E_ + 255) / 256, 256>>>(rows, cols, vals);

    // 3. Chebyshev recurrence
    float* x0 = xbase;
    float* x1 = xbase + (size_t)VF;
    float* x2 = xbase + 2 * (size_t)VF;
    float* x3 = xbase + 3 * (size_t)VF;
    spmm_kernel<<<V_ / 4, 256>>>(x0, x0, x1, 1.0f, 0.0f);   // x1 = L x0
    spmm_kernel<<<V_ / 4, 256>>>(x1, x0, x2, 2.0f, -1.0f);  // x2 = 2 L x1 - x0
    spmm_kernel<<<V_ / 4, 256>>>(x2, x1, x3, 2.0f, -1.0f);  // x3 = 2 L x2 - x1

    // 4. einsum + bias
    einsum_kernel<<<V_ / 4, 256>>>(weight, bias, out);
}

// round 3
// speedup vs baseline: 1.8838x; 1.1273x over previous
#include <cuda_runtime.h>
#include <cstdint>

#define B_    8
#define V_    100000
#define FIN_  32
#define K_    4
#define FOUT_ 64
#define E_    800000
#define TPV   256            // features per vertex = FIN_*B_
#define VF    (V_ * TPV)     // floats per Chebyshev order
#define SCAN_B ((V_ + 1023) / 1024)   // 98 scan blocks

// ---- scratch (static device globals; no allocation) ----
__device__ float d_x[3ull * VF];          // x0..x2 only (x3 lives in shared of fused kernel)
__device__ int   d_counts[V_];
__device__ int   d_rowptr[V_ + 1];
__device__ int   d_cursor[V_];
__device__ int   d_ccol[E_];
__device__ float d_cval[E_];
__device__ int   d_bsum[SCAN_B];

// ---------------- packed f32x2 helpers (Blackwell) ----------------
__device__ __forceinline__ unsigned long long pack2(float a, float b) {
    unsigned long long r;
    asm("mov.b64 %0, {%1, %2};" : "=l"(r) : "f"(a), "f"(b));
    return r;
}
__device__ __forceinline__ unsigned long long fma2(unsigned long long x,
                                                   unsigned long long y,
                                                   unsigned long long c) {
    unsigned long long r;
    asm("fma.rn.f32x2 %0, %1, %2, %3;" : "=l"(r) : "l"(x), "l"(y), "l"(c));
    return r;
}
__device__ __forceinline__ void unpack2(unsigned long long v, float& lo, float& hi) {
    asm("mov.b64 {%0, %1}, %2;" : "=f"(lo), "=f"(hi) : "l"(v));
}

// ---------------- 1. tiled transpose inputs[B,V,Fin] -> x0[v][f*8+b] ----------------
__global__ __launch_bounds__(1024) void transpose_kernel(const float* __restrict__ in) {
    __shared__ float tile[32 * 256 + 32];
    const int v0 = blockIdx.x * 32;
    const int t = threadIdx.x;
    const int lv = t >> 5;
    const int lf = t & 31;
    #pragma unroll
    for (int b = 0; b < B_; b++) {
        float val = in[((size_t)b * V_ + (v0 + lv)) * FIN_ + lf];
        tile[lv * 256 + lf * 8 + b] = val;
    }
    __syncthreads();
    float4* dst = reinterpret_cast<float4*>(&d_x[(size_t)v0 * TPV]);
    const float4* src = reinterpret_cast<const float4*>(tile);
    dst[t] = src[t];
    dst[t + 1024] = src[t + 1024];
}

// ---------------- 2. CSR build ----------------
__global__ void zero_counts_kernel() {
    int i = blockIdx.x * blockDim.x + threadIdx.x;
    if (i < V_) d_counts[i] = 0;
}

__global__ void hist_kernel(const int* __restrict__ rows) {
    int e = blockIdx.x * blockDim.x + threadIdx.x;
    if (e < E_) atomicAdd(&d_counts[rows[e]], 1);
}

__device__ __forceinline__ int block_exscan(int v, int* total) {
    const int lane = threadIdx.x & 31;
    const int wid = threadIdx.x >> 5;
    int inc = v;
    #pragma unroll
    for (int o = 1; o < 32; o <<= 1) {
        int n = __shfl_up_sync(0xffffffffu, inc, o);
        if (lane >= o) inc += n;
    }
    __shared__ int wsum[32];
    if (lane == 31) wsum[wid] = inc;
    __syncthreads();
    if (wid == 0) {
        int s = wsum[lane];
        #pragma unroll
        for (int o = 1; o < 32; o <<= 1) {
            int n = __shfl_up_sync(0xffffffffu, s, o);
            if (lane >= o) s += n;
        }
        wsum[lane] = s;
    }
    __syncthreads();
    int excl = inc - v + (wid ? wsum[wid - 1] : 0);
    *total = wsum[31];
    return excl;
}

__global__ __launch_bounds__(1024) void scan1_kernel() {
    int i = blockIdx.x * 1024 + threadIdx.x;
    int v = (i < V_) ? d_counts[i] : 0;
    int total;
    int excl = block_exscan(v, &total);
    if (i < V_) d_rowptr[i] = excl;
    if (threadIdx.x == 0) d_bsum[blockIdx.x] = total;
}

__global__ void scan2_kernel() {
    __shared__ int s[128];
    int t = threadIdx.x;
    s[t] = (t < SCAN_B) ? d_bsum[t] : 0;
    __syncthreads();
    #pragma unroll
    for (int o = 1; o < 128; o <<= 1) {
        int v = (t >= o) ? s[t - o] : 0;
        __syncthreads();
        s[t] += v;
        __syncthreads();
    }
    if (t < SCAN_B) d_bsum[t] = (t == 0) ? 0 : s[t - 1];
}

__global__ __launch_bounds__(1024) void scan3_kernel() {
    int i = blockIdx.x * 1024 + threadIdx.x;
    if (i < V_) {
        int r = d_rowptr[i] + d_bsum[blockIdx.x];
        d_rowptr[i] = r;
        d_cursor[i] = r;
    }
    if (i == 0) d_rowptr[V_] = E_;
}

__global__ void scatter_kernel(const int* __restrict__ rows,
                               const int* __restrict__ cols,
                               const float* __restrict__ vals) {
    int e = blockIdx.x * blockDim.x + threadIdx.x;
    if (e >= E_) return;
    int r = rows[e];
    int p = atomicAdd(&d_cursor[r], 1);
    d_ccol[p] = cols[e];
    d_cval[p] = vals[e];
}

// ---------------- 3. SpMM passes 1 & 2: y = alpha*(L x) + beta*z ----------------
__global__ __launch_bounds__(256) void spmm_kernel(const float* __restrict__ x,
                                                   const float* __restrict__ z,
                                                   float* __restrict__ y,
                                                   float alpha, float beta) {
    const int g = threadIdx.x >> 6;
    const int t = threadIdx.x & 63;
    const int v = blockIdx.x * 4 + g;
    const int s = __ldg(&d_rowptr[v]);
    const int e = __ldg(&d_rowptr[v + 1]);

    float4 a0 = make_float4(0.f, 0.f, 0.f, 0.f);
    float4 a1 = make_float4(0.f, 0.f, 0.f, 0.f);
    int i = s;
    for (; i + 1 < e; i += 2) {
        int   c0 = __ldg(&d_ccol[i]);
        int   c1 = __ldg(&d_ccol[i + 1]);
        float w0 = __ldg(&d_cval[i]);
        float w1 = __ldg(&d_cval[i + 1]);
        float4 x0 = __ldg(reinterpret_cast<const float4*>(&x[(size_t)c0 * TPV + t * 4]));
        float4 x1 = __ldg(reinterpret_cast<const float4*>(&x[(size_t)c1 * TPV + t * 4]));
        a0.x = fmaf(w0, x0.x, a0.x); a0.y = fmaf(w0, x0.y, a0.y);
        a0.z = fmaf(w0, x0.z, a0.z); a0.w = fmaf(w0, x0.w, a0.w);
        a1.x = fmaf(w1, x1.x, a1.x); a1.y = fmaf(w1, x1.y, a1.y);
        a1.z = fmaf(w1, x1.z, a1.z); a1.w = fmaf(w1, x1.w, a1.w);
    }
    if (i < e) {
        int   c0 = __ldg(&d_ccol[i]);
        float w0 = __ldg(&d_cval[i]);
        float4 x0 = __ldg(reinterpret_cast<const float4*>(&x[(size_t)c0 * TPV + t * 4]));
        a0.x = fmaf(w0, x0.x, a0.x); a0.y = fmaf(w0, x0.y, a0.y);
        a0.z = fmaf(w0, x0.z, a0.z); a0.w = fmaf(w0, x0.w, a0.w);
    }
    float4 r;
    r.x = alpha * (a0.x + a1.x);
    r.y = alpha * (a0.y + a1.y);
    r.z = alpha * (a0.z + a1.z);
    r.w = alpha * (a0.w + a1.w);
    if (beta != 0.f) {
        float4 zv = __ldg(reinterpret_cast<const float4*>(&z[(size_t)v * TPV + t * 4]));
        r.x = fmaf(beta, zv.x, r.x);
        r.y = fmaf(beta, zv.y, r.y);
        r.z = fmaf(beta, zv.z, r.z);
        r.w = fmaf(beta, zv.w, r.w);
    }
    *reinterpret_cast<float4*>(&y[(size_t)v * TPV + t * 4]) = r;
}

// ---------------- 4. FUSED: x3 = 2*L*x2 - x1 (into shared) + einsum + bias ----------------
// Block = 256 threads, 8 vertices. Dynamic shared: ws[8192] | xs[8][4*256]  (64 KB).
// Phase A: one warp per vertex computes x3 and stages x0..x2.
// Phase B: 4 groups of 64 threads; each group handles 2 vertices (weight LDS reused 8x).
__global__ __launch_bounds__(256) void spmm3_einsum_kernel(const float* __restrict__ w,
                                                           const float* __restrict__ bias,
                                                           float* __restrict__ out) {
    extern __shared__ float sm[];
    float* ws = sm;                    // 8192 floats
    float* xs = sm + FIN_ * K_ * FOUT_; // 8 * 1024 floats, xs[v][k*256 + j]

    const int t = threadIdx.x;

    // load weights (independent of phase A)
    #pragma unroll
    for (int i = 0; i < FIN_ * K_ * FOUT_ / 256; i++) ws[i * 256 + t] = w[i * 256 + t];

    // ---- Phase A: SpMM for x3, one warp per vertex ----
    {
        const int sub = t >> 5;        // vertex in block
        const int lane = t & 31;
        const int v = blockIdx.x * 8 + sub;
        const int p0 = lane * 4;       // first float4
        const int p1 = lane * 4 + 128; // second float4
        const float* x2g = d_x + 2ull * VF;
        const float* x1g = d_x + 1ull * VF;
        const float* x0g = d_x;

        const int s = __ldg(&d_rowptr[v]);
        const int e = __ldg(&d_rowptr[v + 1]);
        float4 aA0 = make_float4(0.f, 0.f, 0.f, 0.f);
        float4 aA1 = make_float4(0.f, 0.f, 0.f, 0.f);
        float4 aB0 = make_float4(0.f, 0.f, 0.f, 0.f);
        float4 aB1 = make_float4(0.f, 0.f, 0.f, 0.f);
        int i = s;
        for (; i + 1 < e; i += 2) {
            int   c0 = __ldg(&d_ccol[i]);
            int   c1 = __ldg(&d_ccol[i + 1]);
            float w0 = __ldg(&d_cval[i]);
            float w1 = __ldg(&d_cval[i + 1]);
            float4 u0 = __ldg(reinterpret_cast<const float4*>(&x2g[(size_t)c0 * TPV + p0]));
            float4 u1 = __ldg(reinterpret_cast<const float4*>(&x2g[(size_t)c0 * TPV + p1]));
            float4 v0 = __ldg(reinterpret_cast<const float4*>(&x2g[(size_t)c1 * TPV + p0]));
            float4 v1 = __ldg(reinterpret_cast<const float4*>(&x2g[(size_t)c1 * TPV + p1]));
            aA0.x = fmaf(w0, u0.x, aA0.x); aA0.y = fmaf(w0, u0.y, aA0.y);
            aA0.z = fmaf(w0, u0.z, aA0.z); aA0.w = fmaf(w0, u0.w, aA0.w);
            aA1.x = fmaf(w0, u1.x, aA1.x); aA1.y = fmaf(w0, u1.y, aA1.y);
            aA1.z = fmaf(w0, u1.z, aA1.z); aA1.w = fmaf(w0, u1.w, aA1.w);
            aB0.x = fmaf(w1, v0.x, aB0.x); aB0.y = fmaf(w1, v0.y, aB0.y);
            aB0.z = fmaf(w1, v0.z, aB0.z); aB0.w = fmaf(w1, v0.w, aB0.w);
            aB1.x = fmaf(w1, v1.x, aB1.x); aB1.y = fmaf(w1, v1.y, aB1.y);
            aB1.z = fmaf(w1, v1.z, aB1.z); aB1.w = fmaf(w1, v1.w, aB1.w);
        }
        if (i < e) {
            int   c0 = __ldg(&d_ccol[i]);
            float w0 = __ldg(&d_cval[i]);
            float4 u0 = __ldg(reinterpret_cast<const float4*>(&x2g[(size_t)c0 * TPV + p0]));
            float4 u1 = __ldg(reinterpret_cast<const float4*>(&x2g[(size_t)c0 * TPV + p1]));
            aA0.x = fmaf(w0, u0.x, aA0.x); aA0.y = fmaf(w0, u0.y, aA0.y);
            aA0.z = fmaf(w0, u0.z, aA0.z); aA0.w = fmaf(w0, u0.w, aA0.w);
            aA1.x = fmaf(w0, u1.x, aA1.x); aA1.y = fmaf(w0, u1.y, aA1.y);
            aA1.z = fmaf(w0, u1.z, aA1.z); aA1.w = fmaf(w0, u1.w, aA1.w);
        }
        // stage x0, x1, x2 for this vertex; x3 = 2*(L x2) - x1
        float4 z0 = __ldg(reinterpret_cast<const float4*>(&x1g[(size_t)v * TPV + p0]));
        float4 z1 = __ldg(reinterpret_cast<const float4*>(&x1g[(size_t)v * TPV + p1]));
        float4 r0, r1;
        r0.x = 2.f * (aA0.x + aB0.x) - z0.x;
        r0.y = 2.f * (aA0.y + aB0.y) - z0.y;
        r0.z = 2.f * (aA0.z + aB0.z) - z0.z;
        r0.w = 2.f * (aA0.w + aB0.w) - z0.w;
        r1.x = 2.f * (aA1.x + aB1.x) - z1.x;
        r1.y = 2.f * (aA1.y + aB1.y) - z1.y;
        r1.z = 2.f * (aA1.z + aB1.z) - z1.z;
        r1.w = 2.f * (aA1.w + aB1.w) - z1.w;

        float* xv = xs + sub * (K_ * TPV);
        *reinterpret_cast<float4*>(&xv[0 * TPV + p0]) =
            __ldg(reinterpret_cast<const float4*>(&x0g[(size_t)v * TPV + p0]));
        *reinterpret_cast<float4*>(&xv[0 * TPV + p1]) =
            __ldg(reinterpret_cast<const float4*>(&x0g[(size_t)v * TPV + p1]));
        *reinterpret_cast<float4*>(&xv[1 * TPV + p0]) = z0;
        *reinterpret_cast<float4*>(&xv[1 * TPV + p1]) = z1;
        *reinterpret_cast<float4*>(&xv[2 * TPV + p0]) =
            __ldg(reinterpret_cast<const float4*>(&x2g[(size_t)v * TPV + p0]));
        *reinterpret_cast<float4*>(&xv[2 * TPV + p1]) =
            __ldg(reinterpret_cast<const float4*>(&x2g[(size_t)v * TPV + p1]));
        *reinterpret_cast<float4*>(&xv[3 * TPV + p0]) = r0;
        *reinterpret_cast<float4*>(&xv[3 * TPV + p1]) = r1;
    }
    __syncthreads();

    // ---- Phase B: einsum. 4 groups x 64 threads; each group: 2 vertices ----
    const int g = t >> 6;
    const int o = t & 63;
    const float bo = __ldg(&bias[o]);
    const float* xv0 = xs + (g * 2 + 0) * (K_ * TPV);
    const float* xv1 = xs + (g * 2 + 1) * (K_ * TPV);

    unsigned long long a0[4] = {0ull, 0ull, 0ull, 0ull};
    unsigned long long a1[4] = {0ull, 0ull, 0ull, 0ull};
    #pragma unroll
    for (int k = 0; k < K_; k++) {
        #pragma unroll 4
        for (int f = 0; f < FIN_; f++) {
            float wv = ws[f * (K_ * FOUT_) + k * FOUT_ + o];
            unsigned long long wp = pack2(wv, wv);
            const ulonglong2* q0 = reinterpret_cast<const ulonglong2*>(&xv0[k * TPV + f * 8]);
            const ulonglong2* q1 = reinterpret_cast<const ulonglong2*>(&xv1[k * TPV + f * 8]);
            ulonglong2 p00 = q0[0];
            ulonglong2 p01 = q0[1];
            ulonglong2 p10 = q1[0];
            ulonglong2 p11 = q1[1];
            a0[0] = fma2(p00.x, wp, a0[0]);
            a0[1] = fma2(p00.y, wp, a0[1]);
            a0[2] = fma2(p01.x, wp, a0[2]);
            a0[3] = fma2(p01.y, wp, a0[3]);
            a1[0] = fma2(p10.x, wp, a1[0]);
            a1[1] = fma2(p10.y, wp, a1[1]);
            a1[2] = fma2(p11.x, wp, a1[2]);
            a1[3] = fma2(p11.y, wp, a1[3]);
        }
    }

    const int v0 = blockIdx.x * 8 + g * 2;
    float rb[8];
    #pragma unroll
    for (int j = 0; j < 4; j++) unpack2(a0[j], rb[2 * j], rb[2 * j + 1]);
    #pragma unroll
    for (int b = 0; b < B_; b++)
        out[((size_t)b * V_ + v0) * FOUT_ + o] = rb[b] + bo;
    #pragma unroll
    for (int j = 0; j < 4; j++) unpack2(a1[j], rb[2 * j], rb[2 * j + 1]);
    #pragma unroll
    for (int b = 0; b < B_; b++)
        out[((size_t)b * V_ + v0 + 1) * FOUT_ + o] = rb[b] + bo;
}

// ---------------- launch ----------------
extern "C" void kernel_launch(void* const* d_in, const int* in_sizes, int n_in,
                              void* d_out, int out_size) {
    const float* inputs = (const float*)d_in[0];
    const int*   rows   = (const int*)d_in[1];
    const int*   cols   = (const int*)d_in[2];
    const float* vals   = (const float*)d_in[3];
    const float* weight = (const float*)d_in[4];
    const float* bias   = (const float*)d_in[5];
    float* out = (float*)d_out;

    float* xbase;
    cudaGetSymbolAddress((void**)&xbase, d_x);

    static bool attr_set = false;
    if (!attr_set) {
        cudaFuncSetAttribute(spmm3_einsum_kernel,
                             cudaFuncAttributeMaxDynamicSharedMemorySize, 65536);
        attr_set = true;
    }

    // 1. x0 = transpose(inputs)
    transpose_kernel<<<V_ / 32, 1024>>>(inputs);

    // 2. CSR build
    zero_counts_kernel<<<(V_ + 255) / 256, 256>>>();
    hist_kernel<<<(E_ + 255) / 256, 256>>>(rows);
    scan1_kernel<<<SCAN_B, 1024>>>();
    scan2_kernel<<<1, 128>>>();
    scan3_kernel<<<SCAN_B, 1024>>>();
    scatter_kernel<<<(E_ + 255) / 256, 256>>>(rows, cols, vals);

    // 3. Chebyshev recurrence (passes 1 & 2)
    float* x0 = xbase;
    float* x1 = xbase + (size_t)VF;
    float* x2 = xbase + 2 * (size_t)VF;
    spmm_kernel<<<V_ / 4, 256>>>(x0, x0, x1, 1.0f, 0.0f);   // x1 = L x0
    spmm_kernel<<<V_ / 4, 256>>>(x1, x0, x2, 2.0f, -1.0f);  // x2 = 2 L x1 - x0

    // 4. fused: x3 (shared) + einsum + bias
    spmm3_einsum_kernel<<<V_ / 8, 256, 65536>>>(weight, bias, out);
}